// round 4
// baseline (speedup 1.0000x reference)
#include <cuda_runtime.h>

#define NN 100000
#define NE 1600000
#define BK 64                     // dst nodes per bucket
#define NB ((NN + BK - 1) / BK)   // 1563 buckets

// ---------------- scratch (device globals; no allocation) ----------------
__device__ __align__(16) float g_h[(size_t)NN * 128];  // projected features
__device__ __align__(16) float g_asrc[NN * 4];         // per-node src att logits
__device__ __align__(16) float g_adst[NN * 4];         // per-node dst att logits
__device__ int g_src[NE];
__device__ int g_dst[NE];
__device__ unsigned g_bin[NE];    // packed: src | (dst_local << 17)
__device__ int g_bcnt[NB];
__device__ int g_bofs[NB];
__device__ int g_bcur[NB];
__device__ int g_is64;
__device__ float g_sum[128];
__device__ float g_sq[128];
__device__ __align__(16) float g_scale[128];
__device__ __align__(16) float g_shift[128];

__device__ __forceinline__ float lrelu(float v) { return v > 0.f ? v : 0.2f * v; }

// ---------------- K-zero ----------------
__global__ void k_zero() {
    int t = blockIdx.x * blockDim.x + threadIdx.x;
    if (t < NB) g_bcnt[t] = 0;
    if (t < 128) { g_sum[t] = 0.f; g_sq[t] = 0.f; }
}

// ---------------- K-detect: int64 vs int32 edge_index ----------------
__global__ void k_detect(const unsigned long long* __restrict__ e) {
    if (threadIdx.x == 0 && blockIdx.x == 0) {
        int is64 = 1;
        for (int i = 0; i < 64; i++)
            if (e[i] >= (unsigned long long)NN) { is64 = 0; break; }
        g_is64 = is64;
    }
}

// ---------------- K-convert: int32 src/dst (clamped) + bucket histogram ----------------
__global__ void k_convert(const void* __restrict__ ep) {
    int i = blockIdx.x * blockDim.x + threadIdx.x;
    if (i >= NE) return;
    long long s, d;
    if (g_is64) {
        const long long* e = (const long long*)ep;
        s = e[i]; d = e[NE + i];
    } else {
        const int* e = (const int*)ep;
        s = e[i]; d = e[NE + i];
    }
    if (s < 0) s = 0; if (s > NN - 1) s = NN - 1;
    if (d < 0) d = 0; if (d > NN - 1) d = NN - 1;
    g_src[i] = (int)s;
    g_dst[i] = (int)d;
    atomicAdd(&g_bcnt[(int)d >> 6], 1);
}

// ---------------- K-scan: exclusive scan of bucket counts (1 block) ----------------
__global__ void k_scan() {
    const int CH = 7;               // 256*7 = 1792 >= NB
    __shared__ int part[256];
    int t = threadIdx.x;
    int vals[CH];
    int s = 0;
#pragma unroll
    for (int j = 0; j < CH; j++) {
        int idx = t * CH + j;
        int v = (idx < NB) ? g_bcnt[idx] : 0;
        vals[j] = v; s += v;
    }
    part[t] = s;
    __syncthreads();
    for (int off = 1; off < 256; off <<= 1) {
        int add = (t >= off) ? part[t - off] : 0;
        __syncthreads();
        part[t] += add;
        __syncthreads();
    }
    int excl = part[t] - s;
#pragma unroll
    for (int j = 0; j < CH; j++) {
        int idx = t * CH + j;
        if (idx < NB) { g_bofs[idx] = excl; g_bcur[idx] = excl; }
        excl += vals[j];
    }
}

// ---------------- K-scatter: fill bins with packed (src, dst_local) ----------------
__global__ void k_scatter() {
    int i = blockIdx.x * blockDim.x + threadIdx.x;
    if (i >= NE) return;
    int src = g_src[i], dst = g_dst[i];
    int b = dst >> 6;
    int pos = atomicAdd(&g_bcur[b], 1);
    g_bin[pos] = (unsigned)src | ((unsigned)(dst & 63) << 17);
}

// ---------------- K1: h = x @ W  (fp32 register-tiled GEMM) ----------------
__global__ __launch_bounds__(256) void k_gemm(const float* __restrict__ x,
                                              const float* __restrict__ W) {
    __shared__ float Wsh[32 * 128];   // [kk][c]
    __shared__ float xs[32 * 65];     // [kk][row] (padded)
    int t = threadIdx.x;
    int tx = t & 31, ty = t >> 5;
    int row0 = blockIdx.x * 64;

    float acc[8][4];
#pragma unroll
    for (int i = 0; i < 8; i++)
#pragma unroll
        for (int m = 0; m < 4; m++) acc[i][m] = 0.f;

    for (int c = 0; c < 4; c++) {
        int k0 = c * 32;
        {
            int c4 = t & 31, krb = t >> 5;
            const float4* W4 = (const float4*)W;
#pragma unroll
            for (int j = 0; j < 4; j++) {
                int kr = krb + j * 8;
                ((float4*)Wsh)[kr * 32 + c4] = W4[(k0 + kr) * 32 + c4];
            }
        }
        {
            int rowL = t >> 2, kq = t & 3;
            int gr = row0 + rowL; if (gr > NN - 1) gr = NN - 1;
            const float4* x4 = (const float4*)x;
            float4 v0 = x4[gr * 32 + c * 8 + kq];
            float4 v1 = x4[gr * 32 + c * 8 + kq + 4];
            int kb = kq * 4;
            xs[(kb + 0) * 65 + rowL] = v0.x;
            xs[(kb + 1) * 65 + rowL] = v0.y;
            xs[(kb + 2) * 65 + rowL] = v0.z;
            xs[(kb + 3) * 65 + rowL] = v0.w;
            xs[(kb + 16) * 65 + rowL] = v1.x;
            xs[(kb + 17) * 65 + rowL] = v1.y;
            xs[(kb + 18) * 65 + rowL] = v1.z;
            xs[(kb + 19) * 65 + rowL] = v1.w;
        }
        __syncthreads();
#pragma unroll
        for (int kk = 0; kk < 32; kk++) {
            float wv0 = Wsh[kk * 128 + tx];
            float wv1 = Wsh[kk * 128 + tx + 32];
            float wv2 = Wsh[kk * 128 + tx + 64];
            float wv3 = Wsh[kk * 128 + tx + 96];
#pragma unroll
            for (int i = 0; i < 8; i++) {
                float xv = xs[kk * 65 + ty + 8 * i];
                acc[i][0] += xv * wv0;
                acc[i][1] += xv * wv1;
                acc[i][2] += xv * wv2;
                acc[i][3] += xv * wv3;
            }
        }
        __syncthreads();
    }
#pragma unroll
    for (int i = 0; i < 8; i++) {
        int g = row0 + ty + 8 * i;
        if (g < NN) {
#pragma unroll
            for (int m = 0; m < 4; m++)
                g_h[(size_t)g * 128 + tx + 32 * m] = acc[i][m];
        }
    }
}

// ---------------- K1b: per-node attention logits (warp per node) ----------------
__global__ void k_att(const float* __restrict__ att_src, const float* __restrict__ att_dst) {
    int gw = (blockIdx.x * blockDim.x + threadIdx.x) >> 5;
    if (gw >= NN) return;
    int lane = threadIdx.x & 31;
    float s[4], d[4];
#pragma unroll
    for (int m = 0; m < 4; m++) {
        float hv = g_h[(size_t)gw * 128 + m * 32 + lane];
        s[m] = hv * __ldg(&att_src[m * 32 + lane]);
        d[m] = hv * __ldg(&att_dst[m * 32 + lane]);
    }
    for (int off = 16; off > 0; off >>= 1) {
#pragma unroll
        for (int m = 0; m < 4; m++) {
            s[m] += __shfl_xor_sync(0xffffffffu, s[m], off);
            d[m] += __shfl_xor_sync(0xffffffffu, d[m], off);
        }
    }
    if (lane == 0) {
        *(float4*)&g_asrc[gw * 4] = make_float4(s[0], s[1], s[2], s[3]);
        *(float4*)&g_adst[gw * 4] = make_float4(d[0], d[1], d[2], d[3]);
    }
}

// ---------------- K3: bucketed softmax + aggregation (one block per bucket) ----------------
// Softmax shift-invariance: no segment-max needed (|e| small, exp can't overflow).
// bias before BN cancels exactly -> skipped.
__global__ __launch_bounds__(256) void k_bucket_agg(float* __restrict__ out) {
    __shared__ float feat[BK * 128];   // 32 KB accumulation tile
    __shared__ float den[BK * 4];
    __shared__ float adsm[BK * 4];
    __shared__ float reds[256];
    int b = blockIdx.x;
    int t = threadIdx.x;
    int start = g_bofs[b];
    int end = start + g_bcnt[b];
    int node0 = b * BK;
    int nmax = NN - node0; if (nmax > BK) nmax = BK;

    for (int i = t; i < BK * 128; i += 256) feat[i] = 0.f;
    if (t < BK * 4) {
        int n = t >> 2;
        adsm[t] = (n < nmax) ? g_adst[node0 * 4 + t] : 0.f;
        den[t] = 0.f;
    }
    __syncthreads();

    // pass 1: softmax denominators (thread per edge)
    for (int e = start + t; e < end; e += 256) {
        unsigned p = g_bin[e];
        int src = (int)(p & 0x1FFFFu);
        int dl = (int)(p >> 17);
        float4 s = *(const float4*)&g_asrc[src * 4];
        float w0 = __expf(lrelu(s.x + adsm[dl * 4 + 0]));
        float w1 = __expf(lrelu(s.y + adsm[dl * 4 + 1]));
        float w2 = __expf(lrelu(s.z + adsm[dl * 4 + 2]));
        float w3 = __expf(lrelu(s.w + adsm[dl * 4 + 3]));
        atomicAdd(&den[dl * 4 + 0], w0);
        atomicAdd(&den[dl * 4 + 1], w1);
        atomicAdd(&den[dl * 4 + 2], w2);
        atomicAdd(&den[dl * 4 + 3], w3);
    }
    __syncthreads();
    if (t < BK * 4) den[t] = 1.f / (den[t] + 1e-16f);   // reciprocal once
    __syncthreads();

    // pass 2: alpha-weighted gather-accumulate (warp per edge)
    int wid = t >> 5, lane = t & 31;
    for (int e = start + wid; e < end; e += 8) {
        unsigned p = g_bin[e];
        int src = (int)(p & 0x1FFFFu);
        int dl = (int)(p >> 17);
        float4 s = *(const float4*)&g_asrc[src * 4];
        float a0 = __expf(lrelu(s.x + adsm[dl * 4 + 0])) * den[dl * 4 + 0];
        float a1 = __expf(lrelu(s.y + adsm[dl * 4 + 1])) * den[dl * 4 + 1];
        float a2 = __expf(lrelu(s.z + adsm[dl * 4 + 2])) * den[dl * 4 + 2];
        float a3 = __expf(lrelu(s.w + adsm[dl * 4 + 3])) * den[dl * 4 + 3];
        const float* hrow = &g_h[(size_t)src * 128];
        atomicAdd(&feat[dl * 128 + lane +  0], a0 * __ldg(&hrow[lane +  0]));
        atomicAdd(&feat[dl * 128 + lane + 32], a1 * __ldg(&hrow[lane + 32]));
        atomicAdd(&feat[dl * 128 + lane + 64], a2 * __ldg(&hrow[lane + 64]));
        atomicAdd(&feat[dl * 128 + lane + 96], a3 * __ldg(&hrow[lane + 96]));
    }
    __syncthreads();

    // epilogue: write out tile + fused BN partial sums
    int c = t & 127, half = t >> 7;
    float s = 0.f, q = 0.f;
    for (int r = half; r < nmax; r += 2) {
        float v = feat[r * 128 + c];
        out[(size_t)(node0 + r) * 128 + c] = v;
        s += v; q += v * v;
    }
    reds[t] = s; __syncthreads();
    if (half == 0) atomicAdd(&g_sum[c], s + reds[t + 128]);
    __syncthreads();
    reds[t] = q; __syncthreads();
    if (half == 0) atomicAdd(&g_sq[c], q + reds[t + 128]);
}

// ---------------- K4b: finalize per-channel scale/shift ----------------
__global__ void k_bnfinal(const float* __restrict__ gamma, const float* __restrict__ beta) {
    int c = threadIdx.x;
    float inv_n = 1.f / (float)NN;
    float mu = g_sum[c] * inv_n;
    float var = g_sq[c] * inv_n - mu * mu;
    float inv = rsqrtf(var + 1e-5f);
    float sc = gamma[c] * inv;
    g_scale[c] = sc;
    g_shift[c] = beta[c] - mu * sc;
}

// ---------------- K5: normalize + LeakyReLU (in place on d_out) ----------------
__global__ void k_norm(float* __restrict__ out) {
    int tid = blockIdx.x * blockDim.x + threadIdx.x;
    int stride = gridDim.x * blockDim.x;
    float4* o4 = (float4*)out;
    const float4* sc4 = (const float4*)g_scale;
    const float4* sh4 = (const float4*)g_shift;
    for (int j = tid; j < NN * 32; j += stride) {
        float4 v = o4[j];
        float4 sc = __ldg(&sc4[j & 31]);
        float4 sh = __ldg(&sh4[j & 31]);
        v.x = lrelu(v.x * sc.x + sh.x);
        v.y = lrelu(v.y * sc.y + sh.y);
        v.z = lrelu(v.z * sc.z + sh.z);
        v.w = lrelu(v.w * sc.w + sh.w);
        o4[j] = v;
    }
}

// ---------------- launch ----------------
extern "C" void kernel_launch(void* const* d_in, const int* in_sizes, int n_in,
                              void* d_out, int out_size) {
    const float* x = 0; const void* ei = 0; const float* W = 0;
    const float* att_src = 0; const float* att_dst = 0;
    const float* gamma = 0; const float* beta = 0;
    int n128 = 0;
    for (int i = 0; i < n_in; i++) {
        int sz = in_sizes[i];
        if (sz == NN * 128)        { x = (const float*)d_in[i]; }
        else if (sz == 2 * NE)     { ei = d_in[i]; }
        else if (sz == 128 * 128)  { W = (const float*)d_in[i]; }
        else if (sz == 128) {
            if (n128 == 0)      att_src = (const float*)d_in[i];
            else if (n128 == 1) att_dst = (const float*)d_in[i];
            // n128 == 2 -> bias: cancels exactly under batch-stat BN
            else if (n128 == 3) gamma = (const float*)d_in[i];
            else if (n128 == 4) beta  = (const float*)d_in[i];
            n128++;
        }
    }
    float* out = (float*)d_out;
    if (!x || !ei || !W || !att_src || !att_dst || !gamma || !beta) return;

    k_zero<<<8, 256>>>();
    k_detect<<<1, 32>>>((const unsigned long long*)ei);
    k_convert<<<(NE + 255) / 256, 256>>>(ei);
    k_scan<<<1, 256>>>();
    k_scatter<<<(NE + 255) / 256, 256>>>();
    k_gemm<<<(NN + 63) / 64, 256>>>(x, W);
    k_att<<<(NN + 7) / 8, 256>>>(att_src, att_dst);
    k_bucket_agg<<<NB, 256>>>(out);
    k_bnfinal<<<1, 128>>>(gamma, beta);
    k_norm<<<2048, 256>>>(out);
}

// round 5
// speedup vs baseline: 2.4189x; 2.4189x over previous
#include <cuda_runtime.h>

#define NN 100000
#define NE 1600000
#define SCAN_NT 256
#define SCAN_ITEMS 1024                    // per scan block
#define SCAN_NB ((NN + SCAN_ITEMS - 1) / SCAN_ITEMS)   // 98

// ---------------- scratch (device globals; no allocation) ----------------
__device__ __align__(16) float g_h[(size_t)NN * 128];  // projected features
__device__ __align__(16) float g_asrc[NN * 4];         // per-node src att logits
__device__ __align__(16) float g_adst[NN * 4];         // per-node dst att logits
__device__ int g_src[NE];
__device__ int g_dst[NE];
__device__ int g_bin[NE];                  // src indices grouped by dst (CSR)
__device__ int g_cnt[NN];
__device__ int g_ofs[NN];
__device__ int g_cur[NN];
__device__ int g_part[SCAN_NB];
__device__ int g_pofs[SCAN_NB];
__device__ int g_is64;
__device__ float g_sum[128];
__device__ float g_sq[128];
__device__ __align__(16) float g_scale[128];
__device__ __align__(16) float g_shift[128];

__device__ __forceinline__ float lrelu(float v) { return v > 0.f ? v : 0.2f * v; }

// ---------------- K-zero ----------------
__global__ void k_zero() {
    int t = blockIdx.x * blockDim.x + threadIdx.x;
    if (t < NN) g_cnt[t] = 0;
    if (t < 128) { g_sum[t] = 0.f; g_sq[t] = 0.f; }
}

// ---------------- K-detect: int64 vs int32 edge_index ----------------
__global__ void k_detect(const unsigned long long* __restrict__ e) {
    if (threadIdx.x == 0 && blockIdx.x == 0) {
        int is64 = 1;
        for (int i = 0; i < 64; i++)
            if (e[i] >= (unsigned long long)NN) { is64 = 0; break; }
        g_is64 = is64;
    }
}

// ---------------- K-convert: int32 src/dst (clamped) + per-node histogram ----------------
__global__ void k_convert(const void* __restrict__ ep) {
    int i = blockIdx.x * blockDim.x + threadIdx.x;
    if (i >= NE) return;
    long long s, d;
    if (g_is64) {
        const long long* e = (const long long*)ep;
        s = e[i]; d = e[NE + i];
    } else {
        const int* e = (const int*)ep;
        s = e[i]; d = e[NE + i];
    }
    if (s < 0) s = 0; if (s > NN - 1) s = NN - 1;
    if (d < 0) d = 0; if (d > NN - 1) d = NN - 1;
    g_src[i] = (int)s;
    g_dst[i] = (int)d;
    atomicAdd(&g_cnt[(int)d], 1);
}

// ---------------- 3-kernel exclusive scan of g_cnt -> g_ofs ----------------
__global__ void k_psum() {
    __shared__ int sm[SCAN_NT];
    int b = blockIdx.x, t = threadIdx.x;
    int base = b * SCAN_ITEMS + t * 4;
    int s = 0;
#pragma unroll
    for (int j = 0; j < 4; j++) { int i = base + j; if (i < NN) s += g_cnt[i]; }
    sm[t] = s; __syncthreads();
    for (int off = SCAN_NT / 2; off > 0; off >>= 1) {
        if (t < off) sm[t] += sm[t + off];
        __syncthreads();
    }
    if (t == 0) g_part[b] = sm[0];
}

__global__ void k_scanp() {
    __shared__ int sm[128];
    int t = threadIdx.x;
    int v = (t < SCAN_NB) ? g_part[t] : 0;
    sm[t] = v; __syncthreads();
    for (int off = 1; off < 128; off <<= 1) {
        int a = (t >= off) ? sm[t - off] : 0;
        __syncthreads(); sm[t] += a; __syncthreads();
    }
    if (t < SCAN_NB) g_pofs[t] = sm[t] - v;
}

__global__ void k_base() {
    __shared__ int sm[SCAN_NT];
    int b = blockIdx.x, t = threadIdx.x;
    int base = b * SCAN_ITEMS + t * 4;
    int c[4]; int s = 0;
#pragma unroll
    for (int j = 0; j < 4; j++) {
        int i = base + j;
        c[j] = (i < NN) ? g_cnt[i] : 0;
        s += c[j];
    }
    sm[t] = s; __syncthreads();
    for (int off = 1; off < SCAN_NT; off <<= 1) {
        int a = (t >= off) ? sm[t - off] : 0;
        __syncthreads(); sm[t] += a; __syncthreads();
    }
    int ex = sm[t] - s + g_pofs[b];
#pragma unroll
    for (int j = 0; j < 4; j++) {
        int i = base + j;
        if (i < NN) { g_ofs[i] = ex; g_cur[i] = ex; }
        ex += c[j];
    }
}

// ---------------- K-scatter: CSR fill ----------------
__global__ void k_scatter() {
    int i = blockIdx.x * blockDim.x + threadIdx.x;
    if (i >= NE) return;
    int pos = atomicAdd(&g_cur[g_dst[i]], 1);
    g_bin[pos] = g_src[i];
}

// ---------------- K1: h = x @ W  (fp32 register-tiled GEMM) ----------------
__global__ __launch_bounds__(256) void k_gemm(const float* __restrict__ x,
                                              const float* __restrict__ W) {
    __shared__ float Wsh[32 * 128];
    __shared__ float xs[32 * 65];
    int t = threadIdx.x;
    int tx = t & 31, ty = t >> 5;
    int row0 = blockIdx.x * 64;

    float acc[8][4];
#pragma unroll
    for (int i = 0; i < 8; i++)
#pragma unroll
        for (int m = 0; m < 4; m++) acc[i][m] = 0.f;

    for (int c = 0; c < 4; c++) {
        int k0 = c * 32;
        {
            int c4 = t & 31, krb = t >> 5;
            const float4* W4 = (const float4*)W;
#pragma unroll
            for (int j = 0; j < 4; j++) {
                int kr = krb + j * 8;
                ((float4*)Wsh)[kr * 32 + c4] = W4[(k0 + kr) * 32 + c4];
            }
        }
        {
            int rowL = t >> 2, kq = t & 3;
            int gr = row0 + rowL; if (gr > NN - 1) gr = NN - 1;
            const float4* x4 = (const float4*)x;
            float4 v0 = x4[gr * 32 + c * 8 + kq];
            float4 v1 = x4[gr * 32 + c * 8 + kq + 4];
            int kb = kq * 4;
            xs[(kb + 0) * 65 + rowL] = v0.x;
            xs[(kb + 1) * 65 + rowL] = v0.y;
            xs[(kb + 2) * 65 + rowL] = v0.z;
            xs[(kb + 3) * 65 + rowL] = v0.w;
            xs[(kb + 16) * 65 + rowL] = v1.x;
            xs[(kb + 17) * 65 + rowL] = v1.y;
            xs[(kb + 18) * 65 + rowL] = v1.z;
            xs[(kb + 19) * 65 + rowL] = v1.w;
        }
        __syncthreads();
#pragma unroll
        for (int kk = 0; kk < 32; kk++) {
            float wv0 = Wsh[kk * 128 + tx];
            float wv1 = Wsh[kk * 128 + tx + 32];
            float wv2 = Wsh[kk * 128 + tx + 64];
            float wv3 = Wsh[kk * 128 + tx + 96];
#pragma unroll
            for (int i = 0; i < 8; i++) {
                float xv = xs[kk * 65 + ty + 8 * i];
                acc[i][0] += xv * wv0;
                acc[i][1] += xv * wv1;
                acc[i][2] += xv * wv2;
                acc[i][3] += xv * wv3;
            }
        }
        __syncthreads();
    }
#pragma unroll
    for (int i = 0; i < 8; i++) {
        int g = row0 + ty + 8 * i;
        if (g < NN) {
#pragma unroll
            for (int m = 0; m < 4; m++)
                g_h[(size_t)g * 128 + tx + 32 * m] = acc[i][m];
        }
    }
}

// ---------------- K1b: per-node attention logits (warp per node) ----------------
__global__ void k_att(const float* __restrict__ att_src, const float* __restrict__ att_dst) {
    int gw = (blockIdx.x * blockDim.x + threadIdx.x) >> 5;
    if (gw >= NN) return;
    int lane = threadIdx.x & 31;
    float s[4], d[4];
#pragma unroll
    for (int m = 0; m < 4; m++) {
        float hv = g_h[(size_t)gw * 128 + m * 32 + lane];
        s[m] = hv * __ldg(&att_src[m * 32 + lane]);
        d[m] = hv * __ldg(&att_dst[m * 32 + lane]);
    }
    for (int off = 16; off > 0; off >>= 1) {
#pragma unroll
        for (int m = 0; m < 4; m++) {
            s[m] += __shfl_xor_sync(0xffffffffu, s[m], off);
            d[m] += __shfl_xor_sync(0xffffffffu, d[m], off);
        }
    }
    if (lane == 0) {
        *(float4*)&g_asrc[gw * 4] = make_float4(s[0], s[1], s[2], s[3]);
        *(float4*)&g_adst[gw * 4] = make_float4(d[0], d[1], d[2], d[3]);
    }
}

// ---------------- K3: warp-per-node GAT aggregation, no atomics ----------------
// out_n = (sum_e w_e * h_src[e]) / (sum_e w_e); softmax shift-invariance -> no max pass.
// bias before BN cancels -> skipped. BN partial sums fused into epilogue.
__global__ __launch_bounds__(256) void k_agg(float* __restrict__ out) {
    __shared__ int   ss[8][32];
    __shared__ float ws[8][32 * 4];
    __shared__ float bsum[8][128];
    __shared__ float bsq[8][128];
    int warp = threadIdx.x >> 5, lane = threadIdx.x & 31;
    int n = blockIdx.x * 8 + warp;
    int head = lane >> 3;
    float4 o = make_float4(0.f, 0.f, 0.f, 0.f);

    if (n < NN) {
        int beg = g_ofs[n], cnt = g_cnt[n];
        float4 ad = *(const float4*)&g_adst[n * 4];
        float4 acc = make_float4(0.f, 0.f, 0.f, 0.f);
        float4 den = make_float4(0.f, 0.f, 0.f, 0.f);

        for (int c0 = 0; c0 < cnt; c0 += 32) {
            int m = cnt - c0; if (m > 32) m = 32;
            float4 w = make_float4(0.f, 0.f, 0.f, 0.f);
            int s = 0;
            if (lane < m) {
                s = g_bin[beg + c0 + lane];
                float4 a = *(const float4*)&g_asrc[s * 4];
                w.x = __expf(lrelu(a.x + ad.x));
                w.y = __expf(lrelu(a.y + ad.y));
                w.z = __expf(lrelu(a.z + ad.z));
                w.w = __expf(lrelu(a.w + ad.w));
            }
            ss[warp][lane] = s;
            *(float4*)&ws[warp][lane * 4] = w;
            // denominator: warp-wide sum of w per head
            float4 wr = w;
            for (int off = 16; off > 0; off >>= 1) {
                wr.x += __shfl_xor_sync(0xffffffffu, wr.x, off);
                wr.y += __shfl_xor_sync(0xffffffffu, wr.y, off);
                wr.z += __shfl_xor_sync(0xffffffffu, wr.z, off);
                wr.w += __shfl_xor_sync(0xffffffffu, wr.w, off);
            }
            den.x += wr.x; den.y += wr.y; den.z += wr.z; den.w += wr.w;
            __syncwarp();
            for (int j = 0; j < m; j++) {
                int src = ss[warp][j];
                float wj = ws[warp][j * 4 + head];
                float4 h = *(const float4*)&g_h[(size_t)src * 128 + lane * 4];
                acc.x += wj * h.x;
                acc.y += wj * h.y;
                acc.z += wj * h.z;
                acc.w += wj * h.w;
            }
            __syncwarp();
        }
        float dh = (head == 0) ? den.x : (head == 1) ? den.y : (head == 2) ? den.z : den.w;
        float inv = 1.f / (dh + 1e-16f);
        o = make_float4(acc.x * inv, acc.y * inv, acc.z * inv, acc.w * inv);
        *(float4*)&out[(size_t)n * 128 + lane * 4] = o;
    }

    // fused BN partial sums (per-block reduction, then 256 global atomics)
    *(float4*)&bsum[warp][lane * 4] = o;
    float4 q = make_float4(o.x * o.x, o.y * o.y, o.z * o.z, o.w * o.w);
    *(float4*)&bsq[warp][lane * 4] = q;
    __syncthreads();
    if (threadIdx.x < 128) {
        float s = 0.f, ssq = 0.f;
#pragma unroll
        for (int w2 = 0; w2 < 8; w2++) {
            s += bsum[w2][threadIdx.x];
            ssq += bsq[w2][threadIdx.x];
        }
        atomicAdd(&g_sum[threadIdx.x], s);
        atomicAdd(&g_sq[threadIdx.x], ssq);
    }
}

// ---------------- K4b: finalize per-channel scale/shift ----------------
__global__ void k_bnfinal(const float* __restrict__ gamma, const float* __restrict__ beta) {
    int c = threadIdx.x;
    float inv_n = 1.f / (float)NN;
    float mu = g_sum[c] * inv_n;
    float var = g_sq[c] * inv_n - mu * mu;
    float inv = rsqrtf(var + 1e-5f);
    float sc = gamma[c] * inv;
    g_scale[c] = sc;
    g_shift[c] = beta[c] - mu * sc;
}

// ---------------- K5: normalize + LeakyReLU (in place on d_out) ----------------
__global__ void k_norm(float* __restrict__ out) {
    int tid = blockIdx.x * blockDim.x + threadIdx.x;
    int stride = gridDim.x * blockDim.x;
    float4* o4 = (float4*)out;
    const float4* sc4 = (const float4*)g_scale;
    const float4* sh4 = (const float4*)g_shift;
    for (int j = tid; j < NN * 32; j += stride) {
        float4 v = o4[j];
        float4 sc = __ldg(&sc4[j & 31]);
        float4 sh = __ldg(&sh4[j & 31]);
        v.x = lrelu(v.x * sc.x + sh.x);
        v.y = lrelu(v.y * sc.y + sh.y);
        v.z = lrelu(v.z * sc.z + sh.z);
        v.w = lrelu(v.w * sc.w + sh.w);
        o4[j] = v;
    }
}

// ---------------- launch ----------------
extern "C" void kernel_launch(void* const* d_in, const int* in_sizes, int n_in,
                              void* d_out, int out_size) {
    const float* x = 0; const void* ei = 0; const float* W = 0;
    const float* att_src = 0; const float* att_dst = 0;
    const float* gamma = 0; const float* beta = 0;
    int n128 = 0;
    for (int i = 0; i < n_in; i++) {
        int sz = in_sizes[i];
        if (sz == NN * 128)        { x = (const float*)d_in[i]; }
        else if (sz == 2 * NE)     { ei = d_in[i]; }
        else if (sz == 128 * 128)  { W = (const float*)d_in[i]; }
        else if (sz == 128) {
            if (n128 == 0)      att_src = (const float*)d_in[i];
            else if (n128 == 1) att_dst = (const float*)d_in[i];
            // n128 == 2 -> bias: cancels exactly under batch-stat BN
            else if (n128 == 3) gamma = (const float*)d_in[i];
            else if (n128 == 4) beta  = (const float*)d_in[i];
            n128++;
        }
    }
    float* out = (float*)d_out;
    if (!x || !ei || !W || !att_src || !att_dst || !gamma || !beta) return;

    k_zero<<<(NN + 255) / 256, 256>>>();
    k_detect<<<1, 32>>>((const unsigned long long*)ei);
    k_convert<<<(NE + 255) / 256, 256>>>(ei);
    k_psum<<<SCAN_NB, SCAN_NT>>>();
    k_scanp<<<1, 128>>>();
    k_base<<<SCAN_NB, SCAN_NT>>>();
    k_scatter<<<(NE + 255) / 256, 256>>>();
    k_gemm<<<(NN + 63) / 64, 256>>>(x, W);
    k_att<<<(NN + 7) / 8, 256>>>(att_src, att_dst);
    k_agg<<<(NN + 7) / 8, 256>>>(out);
    k_bnfinal<<<1, 128>>>(gamma, beta);
    k_norm<<<2048, 256>>>(out);
}

// round 6
// speedup vs baseline: 2.6511x; 1.0960x over previous
#include <cuda_runtime.h>

#define NN 100000
#define NE 1600000
#define SCAN_NT 256
#define SCAN_ITEMS 1024
#define SCAN_NB ((NN + SCAN_ITEMS - 1) / SCAN_ITEMS)   // 98

// ---------------- scratch (device globals; no allocation) ----------------
__device__ __align__(16) float g_h[(size_t)NN * 128];  // projected features
__device__ __align__(16) float g_asrc[NN * 4];         // per-node src att logits
__device__ __align__(16) float g_adst[NN * 4];         // per-node dst att logits
__device__ int g_bin[NE];                  // src indices grouped by dst (CSR)
__device__ int g_cnt[NN];
__device__ int g_ofs[NN];
__device__ int g_cur[NN];
__device__ int g_part[SCAN_NB];
__device__ int g_pofs[SCAN_NB];
__device__ int g_is64;
__device__ float g_sum[128];
__device__ float g_sq[128];
__device__ __align__(16) float g_scale[128];
__device__ __align__(16) float g_shift[128];

__device__ __forceinline__ float lrelu(float v) { return v > 0.f ? v : 0.2f * v; }

// ---------------- K-zero ----------------
__global__ void k_zero() {
    int t = blockIdx.x * blockDim.x + threadIdx.x;
    if (t < NN) g_cnt[t] = 0;
    if (t < 128) { g_sum[t] = 0.f; g_sq[t] = 0.f; }
}

// ---------------- K-detect: int64 vs int32 edge_index (parallel ballot) ----------------
// int64 indices < NN in every 8-byte word; int32 data reinterpreted packs two
// indices per word -> almost surely >= 2^32.
__global__ void k_detect(const unsigned long long* __restrict__ e) {
    int lane = threadIdx.x;
    bool good = (e[lane] < (unsigned long long)NN) &&
                (e[32 + lane] < (unsigned long long)NN);
    unsigned b = __ballot_sync(0xffffffffu, good);
    if (lane == 0) g_is64 = (b == 0xffffffffu) ? 1 : 0;
}

// ---------------- K-convert: per-dst histogram (reads dst half only) ----------------
__global__ void k_convert(const void* __restrict__ ep) {
    int i = blockIdx.x * blockDim.x + threadIdx.x;
    if (i >= NE) return;
    long long d;
    if (g_is64) d = ((const long long*)ep)[NE + i];
    else        d = ((const int*)ep)[NE + i];
    if (d < 0) d = 0; if (d > NN - 1) d = NN - 1;
    atomicAdd(&g_cnt[(int)d], 1);
}

// ---------------- 3-kernel exclusive scan of g_cnt -> g_ofs ----------------
__global__ void k_psum() {
    __shared__ int sm[SCAN_NT];
    int b = blockIdx.x, t = threadIdx.x;
    int base = b * SCAN_ITEMS + t * 4;
    int s = 0;
#pragma unroll
    for (int j = 0; j < 4; j++) { int i = base + j; if (i < NN) s += g_cnt[i]; }
    sm[t] = s; __syncthreads();
    for (int off = SCAN_NT / 2; off > 0; off >>= 1) {
        if (t < off) sm[t] += sm[t + off];
        __syncthreads();
    }
    if (t == 0) g_part[b] = sm[0];
}

__global__ void k_scanp() {
    __shared__ int sm[128];
    int t = threadIdx.x;
    int v = (t < SCAN_NB) ? g_part[t] : 0;
    sm[t] = v; __syncthreads();
    for (int off = 1; off < 128; off <<= 1) {
        int a = (t >= off) ? sm[t - off] : 0;
        __syncthreads(); sm[t] += a; __syncthreads();
    }
    if (t < SCAN_NB) g_pofs[t] = sm[t] - v;
}

__global__ void k_base() {
    __shared__ int sm[SCAN_NT];
    int b = blockIdx.x, t = threadIdx.x;
    int base = b * SCAN_ITEMS + t * 4;
    int c[4]; int s = 0;
#pragma unroll
    for (int j = 0; j < 4; j++) {
        int i = base + j;
        c[j] = (i < NN) ? g_cnt[i] : 0;
        s += c[j];
    }
    sm[t] = s; __syncthreads();
    for (int off = 1; off < SCAN_NT; off <<= 1) {
        int a = (t >= off) ? sm[t - off] : 0;
        __syncthreads(); sm[t] += a; __syncthreads();
    }
    int ex = sm[t] - s + g_pofs[b];
#pragma unroll
    for (int j = 0; j < 4; j++) {
        int i = base + j;
        if (i < NN) { g_ofs[i] = ex; g_cur[i] = ex; }
        ex += c[j];
    }
}

// ---------------- K-scatter: CSR fill (reads raw edges directly) ----------------
__global__ void k_scatter(const void* __restrict__ ep) {
    int i = blockIdx.x * blockDim.x + threadIdx.x;
    if (i >= NE) return;
    long long s, d;
    if (g_is64) {
        const long long* e = (const long long*)ep;
        s = e[i]; d = e[NE + i];
    } else {
        const int* e = (const int*)ep;
        s = e[i]; d = e[NE + i];
    }
    if (s < 0) s = 0; if (s > NN - 1) s = NN - 1;
    if (d < 0) d = 0; if (d > NN - 1) d = NN - 1;
    int pos = atomicAdd(&g_cur[(int)d], 1);
    g_bin[pos] = (int)s;
}

// ---------------- K1: h = x @ W (128x128 tile, 8x8 reg) + fused att logits ----------------
// Thread t: tx=t&15 (col pairs tx*2+32m, head-uniform per m), ty=t>>4 (rows ty*8..+8).
__global__ __launch_bounds__(256) void k_gemm_att(const float* __restrict__ x,
                                                  const float* __restrict__ W,
                                                  const float* __restrict__ att_src,
                                                  const float* __restrict__ att_dst) {
    __shared__ float xs[32][132];    // [kk][row] (padded)
    __shared__ float Wsh[32][128];   // [kk][col]
    __shared__ float attb[256];      // [0:128) att_src, [128:256) att_dst
    int t = threadIdx.x;
    int tx = t & 15, ty = t >> 4;
    int row0 = blockIdx.x * 128;
    attb[t] = (t < 128) ? __ldg(&att_src[t]) : __ldg(&att_dst[t - 128]);

    float acc[8][8];
#pragma unroll
    for (int i = 0; i < 8; i++)
#pragma unroll
        for (int j = 0; j < 8; j++) acc[i][j] = 0.f;

    const float4* W4 = (const float4*)W;
    const float4* x4 = (const float4*)x;
    for (int c = 0; c < 4; c++) {
#pragma unroll
        for (int j = 0; j < 4; j++) {           // W chunk [32][128]
            int idx = t * 4 + j;
            int k = idx >> 5, c4 = idx & 31;
            *(float4*)&Wsh[k][c4 * 4] = W4[(c * 32 + k) * 32 + c4];
        }
#pragma unroll
        for (int j = 0; j < 4; j++) {           // x chunk transposed [32][128]
            int idx = t * 4 + j;
            int row = idx >> 3, w8 = idx & 7;
            int gr = row0 + row; if (gr > NN - 1) gr = NN - 1;
            float4 v = x4[(size_t)gr * 32 + c * 8 + w8];
            int kk = w8 * 4;
            xs[kk + 0][row] = v.x;
            xs[kk + 1][row] = v.y;
            xs[kk + 2][row] = v.z;
            xs[kk + 3][row] = v.w;
        }
        __syncthreads();
#pragma unroll
        for (int kk = 0; kk < 32; kk++) {
            float4 xa = *(const float4*)&xs[kk][ty * 8];
            float4 xb = *(const float4*)&xs[kk][ty * 8 + 4];
            float2 w0 = *(const float2*)&Wsh[kk][tx * 2];
            float2 w1 = *(const float2*)&Wsh[kk][tx * 2 + 32];
            float2 w2 = *(const float2*)&Wsh[kk][tx * 2 + 64];
            float2 w3 = *(const float2*)&Wsh[kk][tx * 2 + 96];
            float xv[8] = {xa.x, xa.y, xa.z, xa.w, xb.x, xb.y, xb.z, xb.w};
            float wv[8] = {w0.x, w0.y, w1.x, w1.y, w2.x, w2.y, w3.x, w3.y};
#pragma unroll
            for (int i = 0; i < 8; i++)
#pragma unroll
                for (int j = 0; j < 8; j++) acc[i][j] += xv[i] * wv[j];
        }
        __syncthreads();
    }

    // epilogue: store h + fused per-node attention logits
#pragma unroll
    for (int i = 0; i < 8; i++) {
        int grow = row0 + ty * 8 + i;
        bool valid = grow < NN;
        float s4[4], d4[4];
#pragma unroll
        for (int m = 0; m < 4; m++) {
            int c0 = tx * 2 + 32 * m;
            s4[m] = acc[i][2 * m] * attb[c0] + acc[i][2 * m + 1] * attb[c0 + 1];
            d4[m] = acc[i][2 * m] * attb[128 + c0] + acc[i][2 * m + 1] * attb[128 + c0 + 1];
        }
#pragma unroll
        for (int off = 1; off < 16; off <<= 1) {
#pragma unroll
            for (int m = 0; m < 4; m++) {
                s4[m] += __shfl_xor_sync(0xffffffffu, s4[m], off);
                d4[m] += __shfl_xor_sync(0xffffffffu, d4[m], off);
            }
        }
        if (valid) {
#pragma unroll
            for (int m = 0; m < 4; m++)
                *(float2*)&g_h[(size_t)grow * 128 + tx * 2 + 32 * m] =
                    make_float2(acc[i][2 * m], acc[i][2 * m + 1]);
            if (tx == 0) {
                *(float4*)&g_asrc[grow * 4] = make_float4(s4[0], s4[1], s4[2], s4[3]);
                *(float4*)&g_adst[grow * 4] = make_float4(d4[0], d4[1], d4[2], d4[3]);
            }
        }
    }
}

// ---------------- K3: warp-per-node GAT aggregation, no atomics ----------------
// out_n = (sum_e w_e * h_src[e]) / (sum_e w_e); softmax shift-invariance -> no max pass.
// bias before BN cancels -> skipped. BN partial sums fused into epilogue.
__global__ __launch_bounds__(256) void k_agg(float* __restrict__ out) {
    __shared__ int   ss[8][32];
    __shared__ float ws[8][32 * 4];
    __shared__ float bsum[8][128];
    __shared__ float bsq[8][128];
    int warp = threadIdx.x >> 5, lane = threadIdx.x & 31;
    int n = blockIdx.x * 8 + warp;
    int head = lane >> 3;
    float4 o = make_float4(0.f, 0.f, 0.f, 0.f);

    if (n < NN) {
        int beg = g_ofs[n], cnt = g_cnt[n];
        float4 ad = *(const float4*)&g_adst[n * 4];
        float4 acc = make_float4(0.f, 0.f, 0.f, 0.f);
        float4 den = make_float4(0.f, 0.f, 0.f, 0.f);

        for (int c0 = 0; c0 < cnt; c0 += 32) {
            int m = cnt - c0; if (m > 32) m = 32;
            float4 w = make_float4(0.f, 0.f, 0.f, 0.f);
            int s = 0;
            if (lane < m) {
                s = g_bin[beg + c0 + lane];
                float4 a = *(const float4*)&g_asrc[s * 4];
                w.x = __expf(lrelu(a.x + ad.x));
                w.y = __expf(lrelu(a.y + ad.y));
                w.z = __expf(lrelu(a.z + ad.z));
                w.w = __expf(lrelu(a.w + ad.w));
            }
            ss[warp][lane] = s;
            *(float4*)&ws[warp][lane * 4] = w;
            float4 wr = w;
            for (int off = 16; off > 0; off >>= 1) {
                wr.x += __shfl_xor_sync(0xffffffffu, wr.x, off);
                wr.y += __shfl_xor_sync(0xffffffffu, wr.y, off);
                wr.z += __shfl_xor_sync(0xffffffffu, wr.z, off);
                wr.w += __shfl_xor_sync(0xffffffffu, wr.w, off);
            }
            den.x += wr.x; den.y += wr.y; den.z += wr.z; den.w += wr.w;
            __syncwarp();
            for (int j = 0; j < m; j++) {
                int src = ss[warp][j];
                float wj = ws[warp][j * 4 + head];
                float4 h = *(const float4*)&g_h[(size_t)src * 128 + lane * 4];
                acc.x += wj * h.x;
                acc.y += wj * h.y;
                acc.z += wj * h.z;
                acc.w += wj * h.w;
            }
            __syncwarp();
        }
        float dh = (head == 0) ? den.x : (head == 1) ? den.y : (head == 2) ? den.z : den.w;
        float inv = 1.f / (dh + 1e-16f);
        o = make_float4(acc.x * inv, acc.y * inv, acc.z * inv, acc.w * inv);
        *(float4*)&out[(size_t)n * 128 + lane * 4] = o;
    }

    *(float4*)&bsum[warp][lane * 4] = o;
    float4 q = make_float4(o.x * o.x, o.y * o.y, o.z * o.z, o.w * o.w);
    *(float4*)&bsq[warp][lane * 4] = q;
    __syncthreads();
    if (threadIdx.x < 128) {
        float s = 0.f, ssq = 0.f;
#pragma unroll
        for (int w2 = 0; w2 < 8; w2++) {
            s += bsum[w2][threadIdx.x];
            ssq += bsq[w2][threadIdx.x];
        }
        atomicAdd(&g_sum[threadIdx.x], s);
        atomicAdd(&g_sq[threadIdx.x], ssq);
    }
}

// ---------------- K4b: finalize per-channel scale/shift ----------------
__global__ void k_bnfinal(const float* __restrict__ gamma, const float* __restrict__ beta) {
    int c = threadIdx.x;
    float inv_n = 1.f / (float)NN;
    float mu = g_sum[c] * inv_n;
    float var = g_sq[c] * inv_n - mu * mu;
    float inv = rsqrtf(var + 1e-5f);
    float sc = gamma[c] * inv;
    g_scale[c] = sc;
    g_shift[c] = beta[c] - mu * sc;
}

// ---------------- K5: normalize + LeakyReLU (in place on d_out) ----------------
__global__ void k_norm(float* __restrict__ out) {
    int tid = blockIdx.x * blockDim.x + threadIdx.x;
    int stride = gridDim.x * blockDim.x;
    float4* o4 = (float4*)out;
    const float4* sc4 = (const float4*)g_scale;
    const float4* sh4 = (const float4*)g_shift;
    for (int j = tid; j < NN * 32; j += stride) {
        float4 v = o4[j];
        float4 sc = __ldg(&sc4[j & 31]);
        float4 sh = __ldg(&sh4[j & 31]);
        v.x = lrelu(v.x * sc.x + sh.x);
        v.y = lrelu(v.y * sc.y + sh.y);
        v.z = lrelu(v.z * sc.z + sh.z);
        v.w = lrelu(v.w * sc.w + sh.w);
        o4[j] = v;
    }
}

// ---------------- launch ----------------
extern "C" void kernel_launch(void* const* d_in, const int* in_sizes, int n_in,
                              void* d_out, int out_size) {
    const float* x = 0; const void* ei = 0; const float* W = 0;
    const float* att_src = 0; const float* att_dst = 0;
    const float* gamma = 0; const float* beta = 0;
    int n128 = 0;
    for (int i = 0; i < n_in; i++) {
        int sz = in_sizes[i];
        if (sz == NN * 128)        { x = (const float*)d_in[i]; }
        else if (sz == 2 * NE)     { ei = d_in[i]; }
        else if (sz == 128 * 128)  { W = (const float*)d_in[i]; }
        else if (sz == 128) {
            if (n128 == 0)      att_src = (const float*)d_in[i];
            else if (n128 == 1) att_dst = (const float*)d_in[i];
            // n128 == 2 -> bias: cancels exactly under batch-stat BN
            else if (n128 == 3) gamma = (const float*)d_in[i];
            else if (n128 == 4) beta  = (const float*)d_in[i];
            n128++;
        }
    }
    float* out = (float*)d_out;
    if (!x || !ei || !W || !att_src || !att_dst || !gamma || !beta) return;

    k_zero<<<(NN + 255) / 256, 256>>>();
    k_detect<<<1, 32>>>((const unsigned long long*)ei);
    k_convert<<<(NE + 255) / 256, 256>>>(ei);
    k_psum<<<SCAN_NB, SCAN_NT>>>();
    k_scanp<<<1, 128>>>();
    k_base<<<SCAN_NB, SCAN_NT>>>();
    k_scatter<<<(NE + 255) / 256, 256>>>(ei);
    k_gemm_att<<<(NN + 127) / 128, 256>>>(x, W, att_src, att_dst);
    k_agg<<<(NN + 7) / 8, 256>>>(out);
    k_bnfinal<<<1, 128>>>(gamma, beta);
    k_norm<<<2048, 256>>>(out);
}

// round 7
// speedup vs baseline: 2.8571x; 1.0777x over previous
#include <cuda_runtime.h>
#include <cuda_fp16.h>

#define NN 100000
#define NE 1600000
#define SCAN_NT 256
#define SCAN_ITEMS 1024
#define SCAN_NB ((NN + SCAN_ITEMS - 1) / SCAN_ITEMS)   // 98

// ---------------- scratch (device globals; no allocation) ----------------
__device__ __align__(16) __half g_hh[(size_t)NN * 128];  // projected features (fp16, gather-only)
__device__ __align__(16) float g_asrc[NN * 4];           // per-node src att logits
__device__ __align__(16) float g_adst[NN * 4];           // per-node dst att logits
__device__ int g_bin[NE];                  // src indices grouped by dst (CSR)
__device__ int g_cnt[NN];
__device__ int g_ofs[NN];
__device__ int g_cur[NN];
__device__ int g_part[SCAN_NB];
__device__ int g_pofs[SCAN_NB];
__device__ int g_is64;
__device__ float g_sum[128];
__device__ float g_sq[128];
__device__ __align__(16) float g_scale[128];
__device__ __align__(16) float g_shift[128];

__device__ __forceinline__ float lrelu(float v) { return v > 0.f ? v : 0.2f * v; }

struct __align__(8) h2x2 { __half2 a, b; };

// ---------------- K-zero ----------------
__global__ void k_zero() {
    int t = blockIdx.x * blockDim.x + threadIdx.x;
    if (t < NN) g_cnt[t] = 0;
    if (t < 128) { g_sum[t] = 0.f; g_sq[t] = 0.f; }
}

// ---------------- K-detect: int64 vs int32 edge_index (parallel ballot) ----------------
__global__ void k_detect(const unsigned long long* __restrict__ e) {
    int lane = threadIdx.x;
    bool good = (e[lane] < (unsigned long long)NN) &&
                (e[32 + lane] < (unsigned long long)NN);
    unsigned b = __ballot_sync(0xffffffffu, good);
    if (lane == 0) g_is64 = (b == 0xffffffffu) ? 1 : 0;
}

// ---------------- K-convert: per-dst histogram (reads dst half only) ----------------
__global__ void k_convert(const void* __restrict__ ep) {
    int i = blockIdx.x * blockDim.x + threadIdx.x;
    if (i >= NE) return;
    long long d;
    if (g_is64) d = ((const long long*)ep)[NE + i];
    else        d = ((const int*)ep)[NE + i];
    if (d < 0) d = 0; if (d > NN - 1) d = NN - 1;
    atomicAdd(&g_cnt[(int)d], 1);
}

// ---------------- 3-kernel exclusive scan of g_cnt -> g_ofs ----------------
__global__ void k_psum() {
    __shared__ int sm[SCAN_NT];
    int b = blockIdx.x, t = threadIdx.x;
    int base = b * SCAN_ITEMS + t * 4;
    int s = 0;
#pragma unroll
    for (int j = 0; j < 4; j++) { int i = base + j; if (i < NN) s += g_cnt[i]; }
    sm[t] = s; __syncthreads();
    for (int off = SCAN_NT / 2; off > 0; off >>= 1) {
        if (t < off) sm[t] += sm[t + off];
        __syncthreads();
    }
    if (t == 0) g_part[b] = sm[0];
}

__global__ void k_scanp() {
    __shared__ int sm[128];
    int t = threadIdx.x;
    int v = (t < SCAN_NB) ? g_part[t] : 0;
    sm[t] = v; __syncthreads();
    for (int off = 1; off < 128; off <<= 1) {
        int a = (t >= off) ? sm[t - off] : 0;
        __syncthreads(); sm[t] += a; __syncthreads();
    }
    if (t < SCAN_NB) g_pofs[t] = sm[t] - v;
}

__global__ void k_base() {
    __shared__ int sm[SCAN_NT];
    int b = blockIdx.x, t = threadIdx.x;
    int base = b * SCAN_ITEMS + t * 4;
    int c[4]; int s = 0;
#pragma unroll
    for (int j = 0; j < 4; j++) {
        int i = base + j;
        c[j] = (i < NN) ? g_cnt[i] : 0;
        s += c[j];
    }
    sm[t] = s; __syncthreads();
    for (int off = 1; off < SCAN_NT; off <<= 1) {
        int a = (t >= off) ? sm[t - off] : 0;
        __syncthreads(); sm[t] += a; __syncthreads();
    }
    int ex = sm[t] - s + g_pofs[b];
#pragma unroll
    for (int j = 0; j < 4; j++) {
        int i = base + j;
        if (i < NN) { g_ofs[i] = ex; g_cur[i] = ex; }
        ex += c[j];
    }
}

// ---------------- K-scatter: CSR fill (reads raw edges directly) ----------------
__global__ void k_scatter(const void* __restrict__ ep) {
    int i = blockIdx.x * blockDim.x + threadIdx.x;
    if (i >= NE) return;
    long long s, d;
    if (g_is64) {
        const long long* e = (const long long*)ep;
        s = e[i]; d = e[NE + i];
    } else {
        const int* e = (const int*)ep;
        s = e[i]; d = e[NE + i];
    }
    if (s < 0) s = 0; if (s > NN - 1) s = NN - 1;
    if (d < 0) d = 0; if (d > NN - 1) d = NN - 1;
    int pos = atomicAdd(&g_cur[(int)d], 1);
    g_bin[pos] = (int)s;
}

// ---------------- K1: h = x @ W (128x128 tile, 8x8 reg) + fused att logits ----------------
// Thread t: tx=t&15 (col pairs tx*2+32m, head-uniform per m), ty=t>>4 (rows ty*8..+8).
// h stored fp16 (gather-only consumer); att logits computed from fp32 accs.
__global__ __launch_bounds__(256) void k_gemm_att(const float* __restrict__ x,
                                                  const float* __restrict__ W,
                                                  const float* __restrict__ att_src,
                                                  const float* __restrict__ att_dst) {
    __shared__ float xs[32][132];    // [kk][row] (padded)
    __shared__ float Wsh[32][128];   // [kk][col]
    __shared__ float attb[256];      // [0:128) att_src, [128:256) att_dst
    int t = threadIdx.x;
    int tx = t & 15, ty = t >> 4;
    int row0 = blockIdx.x * 128;
    attb[t] = (t < 128) ? __ldg(&att_src[t]) : __ldg(&att_dst[t - 128]);

    float acc[8][8];
#pragma unroll
    for (int i = 0; i < 8; i++)
#pragma unroll
        for (int j = 0; j < 8; j++) acc[i][j] = 0.f;

    const float4* W4 = (const float4*)W;
    const float4* x4 = (const float4*)x;
    for (int c = 0; c < 4; c++) {
#pragma unroll
        for (int j = 0; j < 4; j++) {           // W chunk [32][128]
            int idx = t * 4 + j;
            int k = idx >> 5, c4 = idx & 31;
            *(float4*)&Wsh[k][c4 * 4] = W4[(c * 32 + k) * 32 + c4];
        }
#pragma unroll
        for (int j = 0; j < 4; j++) {           // x chunk transposed [32][128]
            int idx = t * 4 + j;
            int row = idx >> 3, w8 = idx & 7;
            int gr = row0 + row; if (gr > NN - 1) gr = NN - 1;
            float4 v = x4[(size_t)gr * 32 + c * 8 + w8];
            int kk = w8 * 4;
            xs[kk + 0][row] = v.x;
            xs[kk + 1][row] = v.y;
            xs[kk + 2][row] = v.z;
            xs[kk + 3][row] = v.w;
        }
        __syncthreads();
#pragma unroll
        for (int kk = 0; kk < 32; kk++) {
            float4 xa = *(const float4*)&xs[kk][ty * 8];
            float4 xb = *(const float4*)&xs[kk][ty * 8 + 4];
            float2 w0 = *(const float2*)&Wsh[kk][tx * 2];
            float2 w1 = *(const float2*)&Wsh[kk][tx * 2 + 32];
            float2 w2 = *(const float2*)&Wsh[kk][tx * 2 + 64];
            float2 w3 = *(const float2*)&Wsh[kk][tx * 2 + 96];
            float xv[8] = {xa.x, xa.y, xa.z, xa.w, xb.x, xb.y, xb.z, xb.w};
            float wv[8] = {w0.x, w0.y, w1.x, w1.y, w2.x, w2.y, w3.x, w3.y};
#pragma unroll
            for (int i = 0; i < 8; i++)
#pragma unroll
                for (int j = 0; j < 8; j++) acc[i][j] += xv[i] * wv[j];
        }
        __syncthreads();
    }

    // epilogue: store h (fp16) + fused per-node attention logits (fp32)
    __half2* hh2 = (__half2*)g_hh;
#pragma unroll
    for (int i = 0; i < 8; i++) {
        int grow = row0 + ty * 8 + i;
        bool valid = grow < NN;
        float s4[4], d4[4];
#pragma unroll
        for (int m = 0; m < 4; m++) {
            int c0 = tx * 2 + 32 * m;
            s4[m] = acc[i][2 * m] * attb[c0] + acc[i][2 * m + 1] * attb[c0 + 1];
            d4[m] = acc[i][2 * m] * attb[128 + c0] + acc[i][2 * m + 1] * attb[128 + c0 + 1];
        }
#pragma unroll
        for (int off = 1; off < 16; off <<= 1) {
#pragma unroll
            for (int m = 0; m < 4; m++) {
                s4[m] += __shfl_xor_sync(0xffffffffu, s4[m], off);
                d4[m] += __shfl_xor_sync(0xffffffffu, d4[m], off);
            }
        }
        if (valid) {
#pragma unroll
            for (int m = 0; m < 4; m++)
                hh2[(size_t)grow * 64 + tx + 16 * m] =
                    __float22half2_rn(make_float2(acc[i][2 * m], acc[i][2 * m + 1]));
            if (tx == 0) {
                *(float4*)&g_asrc[grow * 4] = make_float4(s4[0], s4[1], s4[2], s4[3]);
                *(float4*)&g_adst[grow * 4] = make_float4(d4[0], d4[1], d4[2], d4[3]);
            }
        }
    }
}

// ---------------- K3: warp-per-node GAT aggregation, no atomics ----------------
// out_n = (sum_e w_e * h_src[e]) / (sum_e w_e); softmax shift-invariance -> no max pass.
// bias before BN cancels -> skipped. BN partial sums fused into epilogue.
__global__ __launch_bounds__(256) void k_agg(float* __restrict__ out) {
    __shared__ int   ss[8][32];
    __shared__ float ws[8][32 * 4];
    __shared__ float bsum[8][128];
    __shared__ float bsq[8][128];
    int warp = threadIdx.x >> 5, lane = threadIdx.x & 31;
    int n = blockIdx.x * 8 + warp;
    int head = lane >> 3;
    float4 o = make_float4(0.f, 0.f, 0.f, 0.f);

    if (n < NN) {
        int beg = g_ofs[n], cnt = g_cnt[n];
        float4 ad = *(const float4*)&g_adst[n * 4];
        float4 acc = make_float4(0.f, 0.f, 0.f, 0.f);
        float4 den = make_float4(0.f, 0.f, 0.f, 0.f);

        for (int c0 = 0; c0 < cnt; c0 += 32) {
            int m = cnt - c0; if (m > 32) m = 32;
            float4 w = make_float4(0.f, 0.f, 0.f, 0.f);
            int s = 0;
            if (lane < m) {
                s = g_bin[beg + c0 + lane];
                float4 a = *(const float4*)&g_asrc[s * 4];
                w.x = __expf(lrelu(a.x + ad.x));
                w.y = __expf(lrelu(a.y + ad.y));
                w.z = __expf(lrelu(a.z + ad.z));
                w.w = __expf(lrelu(a.w + ad.w));
            }
            ss[warp][lane] = s;
            *(float4*)&ws[warp][lane * 4] = w;
            float4 wr = w;
            for (int off = 16; off > 0; off >>= 1) {
                wr.x += __shfl_xor_sync(0xffffffffu, wr.x, off);
                wr.y += __shfl_xor_sync(0xffffffffu, wr.y, off);
                wr.z += __shfl_xor_sync(0xffffffffu, wr.z, off);
                wr.w += __shfl_xor_sync(0xffffffffu, wr.w, off);
            }
            den.x += wr.x; den.y += wr.y; den.z += wr.z; den.w += wr.w;
            __syncwarp();
            for (int j = 0; j < m; j++) {
                int src = ss[warp][j];
                float wj = ws[warp][j * 4 + head];
                const __half2* hrow = (const __half2*)&g_hh[(size_t)src * 128];
                h2x2 hh = *(const h2x2*)&hrow[lane * 2];
                float2 f0 = __half22float2(hh.a);
                float2 f1 = __half22float2(hh.b);
                acc.x += wj * f0.x;
                acc.y += wj * f0.y;
                acc.z += wj * f1.x;
                acc.w += wj * f1.y;
            }
            __syncwarp();
        }
        float dh = (head == 0) ? den.x : (head == 1) ? den.y : (head == 2) ? den.z : den.w;
        float inv = 1.f / (dh + 1e-16f);
        o = make_float4(acc.x * inv, acc.y * inv, acc.z * inv, acc.w * inv);
        *(float4*)&out[(size_t)n * 128 + lane * 4] = o;
    }

    *(float4*)&bsum[warp][lane * 4] = o;
    float4 q = make_float4(o.x * o.x, o.y * o.y, o.z * o.z, o.w * o.w);
    *(float4*)&bsq[warp][lane * 4] = q;
    __syncthreads();
    if (threadIdx.x < 128) {
        float s = 0.f, ssq = 0.f;
#pragma unroll
        for (int w2 = 0; w2 < 8; w2++) {
            s += bsum[w2][threadIdx.x];
            ssq += bsq[w2][threadIdx.x];
        }
        atomicAdd(&g_sum[threadIdx.x], s);
        atomicAdd(&g_sq[threadIdx.x], ssq);
    }
}

// ---------------- K4b: finalize per-channel scale/shift ----------------
__global__ void k_bnfinal(const float* __restrict__ gamma, const float* __restrict__ beta) {
    int c = threadIdx.x;
    float inv_n = 1.f / (float)NN;
    float mu = g_sum[c] * inv_n;
    float var = g_sq[c] * inv_n - mu * mu;
    float inv = rsqrtf(var + 1e-5f);
    float sc = gamma[c] * inv;
    g_scale[c] = sc;
    g_shift[c] = beta[c] - mu * sc;
}

// ---------------- K5: normalize + LeakyReLU (in place on d_out) ----------------
__global__ void k_norm(float* __restrict__ out) {
    int tid = blockIdx.x * blockDim.x + threadIdx.x;
    int stride = gridDim.x * blockDim.x;
    float4* o4 = (float4*)out;
    const float4* sc4 = (const float4*)g_scale;
    const float4* sh4 = (const float4*)g_shift;
    for (int j = tid; j < NN * 32; j += stride) {
        float4 v = o4[j];
        float4 sc = __ldg(&sc4[j & 31]);
        float4 sh = __ldg(&sh4[j & 31]);
        v.x = lrelu(v.x * sc.x + sh.x);
        v.y = lrelu(v.y * sc.y + sh.y);
        v.z = lrelu(v.z * sc.z + sh.z);
        v.w = lrelu(v.w * sc.w + sh.w);
        o4[j] = v;
    }
}

// ---------------- launch ----------------
extern "C" void kernel_launch(void* const* d_in, const int* in_sizes, int n_in,
                              void* d_out, int out_size) {
    const float* x = 0; const void* ei = 0; const float* W = 0;
    const float* att_src = 0; const float* att_dst = 0;
    const float* gamma = 0; const float* beta = 0;
    int n128 = 0;
    for (int i = 0; i < n_in; i++) {
        int sz = in_sizes[i];
        if (sz == NN * 128)        { x = (const float*)d_in[i]; }
        else if (sz == 2 * NE)     { ei = d_in[i]; }
        else if (sz == 128 * 128)  { W = (const float*)d_in[i]; }
        else if (sz == 128) {
            if (n128 == 0)      att_src = (const float*)d_in[i];
            else if (n128 == 1) att_dst = (const float*)d_in[i];
            // n128 == 2 -> bias: cancels exactly under batch-stat BN
            else if (n128 == 3) gamma = (const float*)d_in[i];
            else if (n128 == 4) beta  = (const float*)d_in[i];
            n128++;
        }
    }
    float* out = (float*)d_out;
    if (!x || !ei || !W || !att_src || !att_dst || !gamma || !beta) return;

    k_zero<<<(NN + 255) / 256, 256>>>();
    k_detect<<<1, 32>>>((const unsigned long long*)ei);
    k_convert<<<(NE + 255) / 256, 256>>>(ei);
    k_psum<<<SCAN_NB, SCAN_NT>>>();
    k_scanp<<<1, 128>>>();
    k_base<<<SCAN_NB, SCAN_NT>>>();
    k_scatter<<<(NE + 255) / 256, 256>>>(ei);
    k_gemm_att<<<(NN + 127) / 128, 256>>>(x, W, att_src, att_dst);
    k_agg<<<(NN + 7) / 8, 256>>>(out);
    k_bnfinal<<<1, 128>>>(gamma, beta);
    k_norm<<<2048, 256>>>(out);
}

// round 8
// speedup vs baseline: 3.6821x; 1.2888x over previous
#include <cuda_runtime.h>
#include <cuda_fp16.h>

#define NN 100000
#define NE 1600000
#define SCAN_NT 256
#define SCAN_ITEMS 1024
#define SCAN_NB ((NN + SCAN_ITEMS - 1) / SCAN_ITEMS)   // 98

// ---------------- scratch (device globals; no allocation) ----------------
__device__ __align__(16) __half g_hh[(size_t)NN * 128];  // projected features (fp16, gather-only)
__device__ __align__(16) float g_asrc[NN * 4];           // per-node src att logits
__device__ __align__(16) float g_adst[NN * 4];           // per-node dst att logits
__device__ int g_bin[NE];                  // src indices grouped by dst (CSR)
__device__ int g_cnt[NN];
__device__ int g_ofs[NN];
__device__ int g_cur[NN];
__device__ int g_part[SCAN_NB];
__device__ int g_pofs[SCAN_NB];
__device__ int g_is64;
__device__ float g_sum[128];
__device__ float g_sq[128];
__device__ __align__(16) float g_scale[128];
__device__ __align__(16) float g_shift[128];

__device__ __forceinline__ float lrelu(float v) { return v > 0.f ? v : 0.2f * v; }
__device__ __forceinline__ unsigned f2tf32(float f) {
    unsigned u;
    asm("cvt.rna.tf32.f32 %0, %1;" : "=r"(u) : "f"(f));
    return u;
}
__device__ __forceinline__ void mma_tf32(float c[4], unsigned a0, unsigned a1,
                                         unsigned a2, unsigned a3,
                                         unsigned b0, unsigned b1) {
    asm volatile(
        "mma.sync.aligned.m16n8k8.row.col.f32.tf32.tf32.f32 "
        "{%0,%1,%2,%3}, {%4,%5,%6,%7}, {%8,%9}, {%0,%1,%2,%3};"
        : "+f"(c[0]), "+f"(c[1]), "+f"(c[2]), "+f"(c[3])
        : "r"(a0), "r"(a1), "r"(a2), "r"(a3), "r"(b0), "r"(b1));
}

struct __align__(8) h2x2 { __half2 a, b; };

// ---------------- K-zero ----------------
__global__ void k_zero() {
    int t = blockIdx.x * blockDim.x + threadIdx.x;
    if (t < NN) g_cnt[t] = 0;
    if (t < 128) { g_sum[t] = 0.f; g_sq[t] = 0.f; }
}

// ---------------- K-detect: int64 vs int32 edge_index (parallel ballot) ----------------
__global__ void k_detect(const unsigned long long* __restrict__ e) {
    int lane = threadIdx.x;
    bool good = (e[lane] < (unsigned long long)NN) &&
                (e[32 + lane] < (unsigned long long)NN);
    unsigned b = __ballot_sync(0xffffffffu, good);
    if (lane == 0) g_is64 = (b == 0xffffffffu) ? 1 : 0;
}

// ---------------- K-convert: per-dst histogram (reads dst half only) ----------------
__global__ void k_convert(const void* __restrict__ ep) {
    int i = blockIdx.x * blockDim.x + threadIdx.x;
    if (i >= NE) return;
    long long d;
    if (g_is64) d = ((const long long*)ep)[NE + i];
    else        d = ((const int*)ep)[NE + i];
    if (d < 0) d = 0; if (d > NN - 1) d = NN - 1;
    atomicAdd(&g_cnt[(int)d], 1);
}

// ---------------- 3-kernel exclusive scan of g_cnt -> g_ofs ----------------
__global__ void k_psum() {
    __shared__ int sm[SCAN_NT];
    int b = blockIdx.x, t = threadIdx.x;
    int base = b * SCAN_ITEMS + t * 4;
    int s = 0;
#pragma unroll
    for (int j = 0; j < 4; j++) { int i = base + j; if (i < NN) s += g_cnt[i]; }
    sm[t] = s; __syncthreads();
    for (int off = SCAN_NT / 2; off > 0; off >>= 1) {
        if (t < off) sm[t] += sm[t + off];
        __syncthreads();
    }
    if (t == 0) g_part[b] = sm[0];
}

__global__ void k_scanp() {
    __shared__ int sm[128];
    int t = threadIdx.x;
    int v = (t < SCAN_NB) ? g_part[t] : 0;
    sm[t] = v; __syncthreads();
    for (int off = 1; off < 128; off <<= 1) {
        int a = (t >= off) ? sm[t - off] : 0;
        __syncthreads(); sm[t] += a; __syncthreads();
    }
    if (t < SCAN_NB) g_pofs[t] = sm[t] - v;
}

__global__ void k_base() {
    __shared__ int sm[SCAN_NT];
    int b = blockIdx.x, t = threadIdx.x;
    int base = b * SCAN_ITEMS + t * 4;
    int c[4]; int s = 0;
#pragma unroll
    for (int j = 0; j < 4; j++) {
        int i = base + j;
        c[j] = (i < NN) ? g_cnt[i] : 0;
        s += c[j];
    }
    sm[t] = s; __syncthreads();
    for (int off = 1; off < SCAN_NT; off <<= 1) {
        int a = (t >= off) ? sm[t - off] : 0;
        __syncthreads(); sm[t] += a; __syncthreads();
    }
    int ex = sm[t] - s + g_pofs[b];
#pragma unroll
    for (int j = 0; j < 4; j++) {
        int i = base + j;
        if (i < NN) { g_ofs[i] = ex; g_cur[i] = ex; }
        ex += c[j];
    }
}

// ---------------- K-scatter: CSR fill (reads raw edges directly) ----------------
__global__ void k_scatter(const void* __restrict__ ep) {
    int i = blockIdx.x * blockDim.x + threadIdx.x;
    if (i >= NE) return;
    long long s, d;
    if (g_is64) {
        const long long* e = (const long long*)ep;
        s = e[i]; d = e[NE + i];
    } else {
        const int* e = (const int*)ep;
        s = e[i]; d = e[NE + i];
    }
    if (s < 0) s = 0; if (s > NN - 1) s = NN - 1;
    if (d < 0) d = 0; if (d > NN - 1) d = NN - 1;
    int pos = atomicAdd(&g_cur[(int)d], 1);
    g_bin[pos] = (int)s;
}

// ---------------- K1: h = x @ W via tf32 mma.sync + fused att logits ----------------
// 128x128 block tile, 8 warps x (16 rows x 128 cols). K chunked by 32.
// A-frag LDS conflict-free with stride 36; B-frag LDS conflict-free with stride 136.
__global__ __launch_bounds__(256) void k_gemm_att(const float* __restrict__ x,
                                                  const float* __restrict__ W,
                                                  const float* __restrict__ att_src,
                                                  const float* __restrict__ att_dst) {
    __shared__ unsigned xs[128][36];   // x chunk [row][k], tf32
    __shared__ unsigned Wsh[32][136];  // W chunk [k][n], tf32
    __shared__ float attb[256];        // [0:128) att_src, [128:256) att_dst
    int t = threadIdx.x;
    int w = t >> 5, lane = t & 31;
    int r0 = w * 16;
    int row0 = blockIdx.x * 128;
    int lg = lane >> 2, lc = lane & 3;
    attb[t] = (t < 128) ? __ldg(&att_src[t]) : __ldg(&att_dst[t - 128]);

    float c[16][4];
#pragma unroll
    for (int nt = 0; nt < 16; nt++)
#pragma unroll
        for (int j = 0; j < 4; j++) c[nt][j] = 0.f;

    const float4* x4 = (const float4*)x;
    const float4* W4 = (const float4*)W;
    for (int ch = 0; ch < 4; ch++) {
        // W chunk [32 k][128 n]: 1024 float4
#pragma unroll
        for (int j = 0; j < 4; j++) {
            int f = t + 256 * j;
            int k = f >> 5, c4 = f & 31;
            float4 v = W4[(ch * 32 + k) * 32 + c4];
            uint4 u = make_uint4(f2tf32(v.x), f2tf32(v.y), f2tf32(v.z), f2tf32(v.w));
            *(uint4*)&Wsh[k][c4 * 4] = u;
        }
        // x chunk [128 rows][32 k]: 1024 float4
#pragma unroll
        for (int j = 0; j < 4; j++) {
            int f = t + 256 * j;
            int row = f >> 3, q = f & 7;
            int gr = row0 + row; if (gr > NN - 1) gr = NN - 1;
            float4 v = x4[(size_t)gr * 32 + ch * 8 + q];
            uint4 u = make_uint4(f2tf32(v.x), f2tf32(v.y), f2tf32(v.z), f2tf32(v.w));
            *(uint4*)&xs[row][q * 4] = u;
        }
        __syncthreads();
#pragma unroll
        for (int ks = 0; ks < 4; ks++) {
            int kc = ks * 8;
            unsigned a0 = xs[r0 + lg][kc + lc];
            unsigned a1 = xs[r0 + lg + 8][kc + lc];
            unsigned a2 = xs[r0 + lg][kc + lc + 4];
            unsigned a3 = xs[r0 + lg + 8][kc + lc + 4];
#pragma unroll
            for (int nt = 0; nt < 16; nt++) {
                unsigned b0 = Wsh[kc + lc][nt * 8 + lg];
                unsigned b1 = Wsh[kc + lc + 4][nt * 8 + lg];
                mma_tf32(c[nt], a0, a1, a2, a3, b0, b1);
            }
        }
        __syncthreads();
    }

    // epilogue: fused attention logits + fp16 h store
    // C layout: c[nt][0,1] -> row r0+lg, cols nt*8+2*lc (+1); c[nt][2,3] -> row+8.
    float s1[4] = {0,0,0,0}, s2[4] = {0,0,0,0};
    float d1[4] = {0,0,0,0}, d2[4] = {0,0,0,0};
#pragma unroll
    for (int m = 0; m < 4; m++) {
#pragma unroll
        for (int q = 0; q < 4; q++) {
            int nt = m * 4 + q;
            int col = nt * 8 + 2 * lc;
            float as0 = attb[col], as1 = attb[col + 1];
            float ad0 = attb[128 + col], ad1 = attb[128 + col + 1];
            s1[m] += c[nt][0] * as0 + c[nt][1] * as1;
            d1[m] += c[nt][0] * ad0 + c[nt][1] * ad1;
            s2[m] += c[nt][2] * as0 + c[nt][3] * as1;
            d2[m] += c[nt][2] * ad0 + c[nt][3] * ad1;
        }
    }
#pragma unroll
    for (int off = 1; off <= 2; off <<= 1) {
#pragma unroll
        for (int m = 0; m < 4; m++) {
            s1[m] += __shfl_xor_sync(0xffffffffu, s1[m], off);
            s2[m] += __shfl_xor_sync(0xffffffffu, s2[m], off);
            d1[m] += __shfl_xor_sync(0xffffffffu, d1[m], off);
            d2[m] += __shfl_xor_sync(0xffffffffu, d2[m], off);
        }
    }
    int rowA = row0 + r0 + lg;
    int rowB = rowA + 8;
    if (lc == 0) {
        if (rowA < NN) {
            *(float4*)&g_asrc[rowA * 4] = make_float4(s1[0], s1[1], s1[2], s1[3]);
            *(float4*)&g_adst[rowA * 4] = make_float4(d1[0], d1[1], d1[2], d1[3]);
        }
        if (rowB < NN) {
            *(float4*)&g_asrc[rowB * 4] = make_float4(s2[0], s2[1], s2[2], s2[3]);
            *(float4*)&g_adst[rowB * 4] = make_float4(d2[0], d2[1], d2[2], d2[3]);
        }
    }
    __half2* hh2 = (__half2*)g_hh;
    if (rowA < NN) {
#pragma unroll
        for (int nt = 0; nt < 16; nt++)
            hh2[(size_t)rowA * 64 + nt * 4 + lc] =
                __float22half2_rn(make_float2(c[nt][0], c[nt][1]));
    }
    if (rowB < NN) {
#pragma unroll
        for (int nt = 0; nt < 16; nt++)
            hh2[(size_t)rowB * 64 + nt * 4 + lc] =
                __float22half2_rn(make_float2(c[nt][2], c[nt][3]));
    }
}

// ---------------- K3: warp-per-node GAT aggregation, no atomics ----------------
__global__ __launch_bounds__(256) void k_agg(float* __restrict__ out) {
    __shared__ int   ss[8][32];
    __shared__ float ws[8][32 * 4];
    __shared__ float bsum[8][128];
    __shared__ float bsq[8][128];
    int warp = threadIdx.x >> 5, lane = threadIdx.x & 31;
    int n = blockIdx.x * 8 + warp;
    int head = lane >> 3;
    float4 o = make_float4(0.f, 0.f, 0.f, 0.f);

    if (n < NN) {
        int beg = g_ofs[n], cnt = g_cnt[n];
        float4 ad = *(const float4*)&g_adst[n * 4];
        float4 acc = make_float4(0.f, 0.f, 0.f, 0.f);
        float4 den = make_float4(0.f, 0.f, 0.f, 0.f);

        for (int c0 = 0; c0 < cnt; c0 += 32) {
            int m = cnt - c0; if (m > 32) m = 32;
            float4 w = make_float4(0.f, 0.f, 0.f, 0.f);
            int s = 0;
            if (lane < m) {
                s = g_bin[beg + c0 + lane];
                float4 a = *(const float4*)&g_asrc[s * 4];
                w.x = __expf(lrelu(a.x + ad.x));
                w.y = __expf(lrelu(a.y + ad.y));
                w.z = __expf(lrelu(a.z + ad.z));
                w.w = __expf(lrelu(a.w + ad.w));
            }
            ss[warp][lane] = s;
            *(float4*)&ws[warp][lane * 4] = w;
            float4 wr = w;
            for (int off = 16; off > 0; off >>= 1) {
                wr.x += __shfl_xor_sync(0xffffffffu, wr.x, off);
                wr.y += __shfl_xor_sync(0xffffffffu, wr.y, off);
                wr.z += __shfl_xor_sync(0xffffffffu, wr.z, off);
                wr.w += __shfl_xor_sync(0xffffffffu, wr.w, off);
            }
            den.x += wr.x; den.y += wr.y; den.z += wr.z; den.w += wr.w;
            __syncwarp();
            for (int j = 0; j < m; j++) {
                int src = ss[warp][j];
                float wj = ws[warp][j * 4 + head];
                const __half2* hrow = (const __half2*)&g_hh[(size_t)src * 128];
                h2x2 hh = *(const h2x2*)&hrow[lane * 2];
                float2 f0 = __half22float2(hh.a);
                float2 f1 = __half22float2(hh.b);
                acc.x += wj * f0.x;
                acc.y += wj * f0.y;
                acc.z += wj * f1.x;
                acc.w += wj * f1.y;
            }
            __syncwarp();
        }
        float dh = (head == 0) ? den.x : (head == 1) ? den.y : (head == 2) ? den.z : den.w;
        float inv = 1.f / (dh + 1e-16f);
        o = make_float4(acc.x * inv, acc.y * inv, acc.z * inv, acc.w * inv);
        *(float4*)&out[(size_t)n * 128 + lane * 4] = o;
    }

    *(float4*)&bsum[warp][lane * 4] = o;
    float4 q = make_float4(o.x * o.x, o.y * o.y, o.z * o.z, o.w * o.w);
    *(float4*)&bsq[warp][lane * 4] = q;
    __syncthreads();
    if (threadIdx.x < 128) {
        float s = 0.f, ssq = 0.f;
#pragma unroll
        for (int w2 = 0; w2 < 8; w2++) {
            s += bsum[w2][threadIdx.x];
            ssq += bsq[w2][threadIdx.x];
        }
        atomicAdd(&g_sum[threadIdx.x], s);
        atomicAdd(&g_sq[threadIdx.x], ssq);
    }
}

// ---------------- K4b: finalize per-channel scale/shift ----------------
__global__ void k_bnfinal(const float* __restrict__ gamma, const float* __restrict__ beta) {
    int c = threadIdx.x;
    float inv_n = 1.f / (float)NN;
    float mu = g_sum[c] * inv_n;
    float var = g_sq[c] * inv_n - mu * mu;
    float inv = rsqrtf(var + 1e-5f);
    float sc = gamma[c] * inv;
    g_scale[c] = sc;
    g_shift[c] = beta[c] - mu * sc;
}

// ---------------- K5: normalize + LeakyReLU (in place on d_out) ----------------
__global__ void k_norm(float* __restrict__ out) {
    int tid = blockIdx.x * blockDim.x + threadIdx.x;
    int stride = gridDim.x * blockDim.x;
    float4* o4 = (float4*)out;
    const float4* sc4 = (const float4*)g_scale;
    const float4* sh4 = (const float4*)g_shift;
    for (int j = tid; j < NN * 32; j += stride) {
        float4 v = o4[j];
        float4 sc = __ldg(&sc4[j & 31]);
        float4 sh = __ldg(&sh4[j & 31]);
        v.x = lrelu(v.x * sc.x + sh.x);
        v.y = lrelu(v.y * sc.y + sh.y);
        v.z = lrelu(v.z * sc.z + sh.z);
        v.w = lrelu(v.w * sc.w + sh.w);
        o4[j] = v;
    }
}

// ---------------- launch ----------------
extern "C" void kernel_launch(void* const* d_in, const int* in_sizes, int n_in,
                              void* d_out, int out_size) {
    const float* x = 0; const void* ei = 0; const float* W = 0;
    const float* att_src = 0; const float* att_dst = 0;
    const float* gamma = 0; const float* beta = 0;
    int n128 = 0;
    for (int i = 0; i < n_in; i++) {
        int sz = in_sizes[i];
        if (sz == NN * 128)        { x = (const float*)d_in[i]; }
        else if (sz == 2 * NE)     { ei = d_in[i]; }
        else if (sz == 128 * 128)  { W = (const float*)d_in[i]; }
        else if (sz == 128) {
            if (n128 == 0)      att_src = (const float*)d_in[i];
            else if (n128 == 1) att_dst = (const float*)d_in[i];
            // n128 == 2 -> bias: cancels exactly under batch-stat BN
            else if (n128 == 3) gamma = (const float*)d_in[i];
            else if (n128 == 4) beta  = (const float*)d_in[i];
            n128++;
        }
    }
    float* out = (float*)d_out;
    if (!x || !ei || !W || !att_src || !att_dst || !gamma || !beta) return;

    k_zero<<<(NN + 255) / 256, 256>>>();
    k_detect<<<1, 32>>>((const unsigned long long*)ei);
    k_convert<<<(NE + 255) / 256, 256>>>(ei);
    k_psum<<<SCAN_NB, SCAN_NT>>>();
    k_scanp<<<1, 128>>>();
    k_base<<<SCAN_NB, SCAN_NT>>>();
    k_scatter<<<(NE + 255) / 256, 256>>>(ei);
    k_gemm_att<<<(NN + 127) / 128, 256>>>(x, W, att_src, att_dst);
    k_agg<<<(NN + 7) / 8, 256>>>(out);
    k_bnfinal<<<1, 128>>>(gamma, beta);
    k_norm<<<2048, 256>>>(out);
}